// round 5
// baseline (speedup 1.0000x reference)
#include <cuda_runtime.h>

// BinsChamferLoss: n=16, d=128, h=192, w=256.  Single fused kernel.
// out[b] = (loss1[b] + loss2[b]) / sum(valid_mask)   (count over ALL batches)
//   g = valid ? max(t, bins[b][0]) : bins[b][0]
//   loss1[b] = sum_pixels min_bins |g - bin|   (7-level Eytzinger search,
//                                               top 2 levels in registers)
//   loss2[b] = sum_bins  min_pixels |g - bin|  (segment min/max + prefix/suffix)
//
// R5: occupancy was the binding constraint (occ=30%, issue=30%, all pipes idle).
// Grid doubled (BPB 24->48), search shortened to 5 LDS steps.

#define NB   16
#define DB   128
#define HW   49152            // 192*256
#define BPB  48               // blocks per batch
#define PPB  (HW / BPB)       // 1024 pixels per block
#define TH   256
#define NSEG (DB + 1)         // segment s in [1,128]; slot 0 unused
#define INF_BITS 0x7F800000

// Per-block partials (no init required; fully overwritten every replay).
__device__ float        g_pl1 [NB * BPB];
__device__ unsigned int g_pcnt[NB * BPB];
__device__ int          g_pmax[NB * BPB * NSEG];   // float bits; -1 = empty
__device__ int          g_pmin[NB * BPB * NSEG];   // INF_BITS = empty
// Per-batch results + tickets (reset to 0 by their last user each replay).
__device__ float        g_bsum[NB];
__device__ unsigned int g_bcnt[NB];
__device__ unsigned int g_tick_b[NB];
__device__ unsigned int g_tick_g;

// upper_bound over sb[0..127] (sb[0] <= g guaranteed): returns s in [1,128],
// the first index with sb[s] > g.  lvl0=sb[64], lvl1a=sb[32], lvl1b=sb[96];
// ez holds the remaining 5 levels (nodes 4..127 of the 127-node tree).
__device__ __forceinline__ int ub7(float g, float lvl0, float lvl1a, float lvl1b,
                                   const float* ez) {
    const int c0 = (lvl0 <= g);
    int n = 2 + c0;
    const float v1 = c0 ? lvl1b : lvl1a;
    n = 2 * n + (v1 <= g);                 // n in [4,8)
    #pragma unroll
    for (int bs = 0; bs < 5; bs++) n = 2 * n + (ez[n] <= g);
    return n - 127;                        // n in [128,256)
}

__global__ __launch_bounds__(TH) void bcl_fused(const float* __restrict__ bins,
                                                const float* __restrict__ tdm,
                                                const int*   __restrict__ mask,
                                                float*       __restrict__ out) {
    const int batch = blockIdx.x / BPB;
    const int blk   = blockIdx.x % BPB;
    const int bid   = blockIdx.x;
    const int tid   = threadIdx.x;

    __shared__ float sb[NSEG];          // sorted bins + inf pad (for distances)
    __shared__ float ez[128];           // Eytzinger tree nodes 1..127 (0 unused)
    __shared__ int   spmax[NSEG];
    __shared__ int   spmin[NSEG];
    __shared__ int   sflag;             // any invalid pixel seen
    __shared__ float        wl[TH / 32];
    __shared__ unsigned int wc[TH / 32];
    __shared__ unsigned int s_tick;

    if (tid < DB)   sb[tid] = bins[batch * DB + tid];
    if (tid == DB)  sb[DB]  = __int_as_float(INF_BITS);
    for (int i = tid; i < NSEG; i += TH) { spmax[i] = -1; spmin[i] = INF_BITS; }
    if (tid == 0) { sflag = 0; ez[0] = 0.0f; }
    __syncthreads();

    // Build 127-node BFS tree over ranks 1..127: node i at depth d holds
    // rank r = (i - 2^d)*2^(7-d) + 2^(6-d)  (always in [1,127]).
    if (tid >= 1 && tid < 128) {
        const int d = 31 - __clz(tid);
        const int r = ((tid - (1 << d)) << (7 - d)) + (1 << (6 - d));
        ez[tid] = sb[r];
    }
    __syncthreads();

    const float b0    = sb[0];
    const float lvl0  = sb[64];
    const float lvl1a = sb[32];
    const float lvl1b = sb[96];

    float loss1 = 0.0f;
    unsigned int cnt = 0;
    bool sawInvalid = false;

    const int base = batch * HW + blk * PPB;
    const float4 tv = ((const float4*)(tdm + base))[tid];
    const int4   mv = ((const int4*)(mask + base))[tid];
    const float gv[4] = {tv.x, tv.y, tv.z, tv.w};
    const int   mk[4] = {mv.x, mv.y, mv.z, mv.w};

    #pragma unroll
    for (int k = 0; k < 4; k++) {
        const bool valid = (mk[k] != 0);
        const float g = valid ? fmaxf(gv[k], b0) : b0;
        const int s = ub7(g, lvl0, lvl1a, lvl1b, ez);
        loss1 += fminf(g - sb[s - 1], sb[s] - g);        // 0 for invalid (g==b0)
        if (valid) {
            cnt++;
            const int gi = __float_as_int(g);            // g>0: int order == float order
            if (gi > spmax[s]) atomicMax(&spmax[s], gi); // monotonic: race-safe
            if (gi < spmin[s]) atomicMin(&spmin[s], gi);
        } else {
            sawInvalid = true;
        }
    }
    if (sawInvalid) sflag = 1;                           // benign race
    __syncthreads();

    if (tid == 0 && sflag) {                             // one b0 update for all invalids
        const int s = ub7(b0, lvl0, lvl1a, lvl1b, ez);
        const int bi = __float_as_int(b0);
        if (bi > spmax[s]) atomicMax(&spmax[s], bi);
        if (bi < spmin[s]) atomicMin(&spmin[s], bi);
    }

    // block reduce loss1 & count
    #pragma unroll
    for (int off = 16; off; off >>= 1) {
        loss1 += __shfl_down_sync(0xFFFFFFFFu, loss1, off);
        cnt   += __shfl_down_sync(0xFFFFFFFFu, cnt,   off);
    }
    if ((tid & 31) == 0) { wl[tid >> 5] = loss1; wc[tid >> 5] = cnt; }
    __syncthreads();

    // publish partials
    if (tid == 0) {
        float L = 0.0f; unsigned int C = 0;
        #pragma unroll
        for (int w = 0; w < TH / 32; w++) { L += wl[w]; C += wc[w]; }
        g_pl1[bid] = L; g_pcnt[bid] = C;
    }
    for (int i = tid; i < NSEG; i += TH) {
        g_pmax[bid * NSEG + i] = spmax[i];
        g_pmin[bid * NSEG + i] = spmin[i];
    }
    __threadfence();
    if (tid == 0) s_tick = atomicAdd(&g_tick_b[batch], 1u);
    __syncthreads();
    if (s_tick != BPB - 1) return;

    // ---------------- batch finalizer (one block per batch) ----------------
    __threadfence();
    if (tid == 0) g_tick_b[batch] = 0;                   // reset for next replay

    __shared__ float pref[NSEG], suf[NSEG];
    for (int i = tid; i < 2 * NSEG; i += TH) {
        const int seg = i >> 1;
        const int mbase = (batch * BPB) * NSEG + seg;
        if ((i & 1) == 0) {
            int mx = -1;
            #pragma unroll 8
            for (int b = 0; b < BPB; b++) mx = max(mx, g_pmax[mbase + b * NSEG]);
            pref[seg] = (mx == -1) ? -1e30f : __int_as_float(mx);
        } else {
            int mn = INF_BITS;
            #pragma unroll 8
            for (int b = 0; b < BPB; b++) mn = min(mn, g_pmin[mbase + b * NSEG]);
            suf[seg] = (mn == INF_BITS) ? 1e30f : __int_as_float(mn);
        }
    }
    float L = 0.0f; unsigned int C = 0;
    if (tid < 64) {
        if (tid < BPB) { L = g_pl1[batch * BPB + tid]; C = g_pcnt[batch * BPB + tid]; }
        #pragma unroll
        for (int off = 16; off; off >>= 1) {
            L += __shfl_down_sync(0xFFFFFFFFu, L, off);
            C += __shfl_down_sync(0xFFFFFFFFu, C, off);
        }
    }
    __syncthreads();
    if (tid < 64 && (tid & 31) == 0) { wl[tid >> 5] = L; wc[tid >> 5] = C; }
    __syncthreads();

    if (tid == 0) {                                      // in-place 129-entry scans
        float r = -1e30f;
        for (int s = 0; s < NSEG; s++) { r = fmaxf(r, pref[s]); pref[s] = r; }
        float r2 = 1e30f;
        for (int s = NSEG - 1; s >= 0; s--) { r2 = fminf(r2, suf[s]); suf[s] = r2; }
    }
    __syncthreads();

    float v = 0.0f;
    if (tid < DB) {
        const float bj = sb[tid];
        v = fminf(bj - pref[tid], suf[tid + 1] - bj);    // exact per-bin min dist
    }
    #pragma unroll
    for (int off = 16; off; off >>= 1) v += __shfl_down_sync(0xFFFFFFFFu, v, off);
    __shared__ float wv[TH / 32];
    if ((tid & 31) == 0) wv[tid >> 5] = v;
    __syncthreads();

    if (tid == 0) {
        const float loss2 = wv[0] + wv[1] + wv[2] + wv[3];
        g_bsum[batch] = (wl[0] + wl[1]) + loss2;
        g_bcnt[batch] = wc[0] + wc[1];
        __threadfence();
        const unsigned int t2 = atomicAdd(&g_tick_g, 1u);
        if (t2 == NB - 1) {                              // global finalizer
            g_tick_g = 0;
            __threadfence();
            unsigned int tot = 0;
            #pragma unroll
            for (int b = 0; b < NB; b++) tot += g_bcnt[b];
            const float inv = 1.0f / (float)tot;
            #pragma unroll
            for (int b = 0; b < NB; b++) out[b] = g_bsum[b] * inv;
        }
    }
}

extern "C" void kernel_launch(void* const* d_in, const int* in_sizes, int n_in,
                              void* d_out, int out_size) {
    const float* bins = (const float*)d_in[0];
    const float* tdm  = (const float*)d_in[1];
    const int*   msk  = (const int*)d_in[2];
    float*       out  = (float*)d_out;

    bcl_fused<<<NB * BPB, TH>>>(bins, tdm, msk, out);
}

// round 6
// speedup vs baseline: 1.3108x; 1.3108x over previous
#include <cuda_runtime.h>

// BinsChamferLoss: n=16, d=128, h=192, w=256.  Single fused kernel.
// out[b] = (loss1[b] + loss2[b]) / sum(valid_mask)   (count over ALL batches)
//   g = valid ? max(t, bins[b][0]) : bins[b][0]
//   loss1[b] = sum_pixels min_bins |g - bin|   (7-level Eytzinger search,
//                                               top 2 levels in registers)
//   loss2[b] = sum_bins  min_pixels |g - bin|  (segment min/max + PARALLEL
//                                               prefix-max / suffix-min scans)
//
// R6: the tail was a single-thread 258-iteration dependent scan (~9K cycles)
// present since R2 — replaced with a Hillis-Steele scan. BPB back to 24.

#define NB   16
#define DB   128
#define HW   49152            // 192*256
#define BPB  24               // blocks per batch
#define PPB  (HW / BPB)       // 2048 pixels per block
#define TH   256
#define NSEG (DB + 1)         // segment s in [1,128]; slot 0 unused
#define INF_BITS 0x7F800000

// Per-block partials (no init required; fully overwritten every replay).
__device__ float        g_pl1 [NB * BPB];
__device__ unsigned int g_pcnt[NB * BPB];
__device__ int          g_pmax[NB * BPB * NSEG];   // float bits; -1 = empty
__device__ int          g_pmin[NB * BPB * NSEG];   // INF_BITS = empty
// Per-batch results + tickets (reset to 0 by their last user each replay).
__device__ float        g_bsum[NB];
__device__ unsigned int g_bcnt[NB];
__device__ unsigned int g_tick_b[NB];
__device__ unsigned int g_tick_g;

// upper_bound over sb[0..127] (sb[0] <= g guaranteed): returns s in [1,128],
// the first index with sb[s] > g.  lvl0=sb[64], lvl1a=sb[32], lvl1b=sb[96];
// ez holds the remaining 5 levels (nodes 4..127 of the 127-node tree).
__device__ __forceinline__ int ub7(float g, float lvl0, float lvl1a, float lvl1b,
                                   const float* ez) {
    const int c0 = (lvl0 <= g);
    int n = 2 + c0;
    const float v1 = c0 ? lvl1b : lvl1a;
    n = 2 * n + (v1 <= g);                 // n in [4,8)
    #pragma unroll
    for (int bs = 0; bs < 5; bs++) n = 2 * n + (ez[n] <= g);
    return n - 127;                        // n in [128,256)
}

__global__ __launch_bounds__(TH) void bcl_fused(const float* __restrict__ bins,
                                                const float* __restrict__ tdm,
                                                const int*   __restrict__ mask,
                                                float*       __restrict__ out) {
    const int batch = blockIdx.x / BPB;
    const int blk   = blockIdx.x % BPB;
    const int bid   = blockIdx.x;
    const int tid   = threadIdx.x;

    __shared__ float sb[NSEG];          // sorted bins + inf pad (for distances)
    __shared__ float ez[128];           // Eytzinger tree nodes 1..127 (0 unused)
    __shared__ int   spmax[NSEG];
    __shared__ int   spmin[NSEG];
    __shared__ int   sflag;             // any invalid pixel seen
    __shared__ float        wl[TH / 32];
    __shared__ unsigned int wc[TH / 32];
    __shared__ unsigned int s_tick;

    if (tid < DB)   sb[tid] = bins[batch * DB + tid];
    if (tid == DB)  sb[DB]  = __int_as_float(INF_BITS);
    for (int i = tid; i < NSEG; i += TH) { spmax[i] = -1; spmin[i] = INF_BITS; }
    if (tid == 0) { sflag = 0; ez[0] = 0.0f; }
    __syncthreads();

    // Build 127-node BFS tree over ranks 1..127: node i at depth d holds
    // rank r = (i - 2^d)*2^(7-d) + 2^(6-d)  (always in [1,127]).
    if (tid >= 1 && tid < 128) {
        const int d = 31 - __clz(tid);
        const int r = ((tid - (1 << d)) << (7 - d)) + (1 << (6 - d));
        ez[tid] = sb[r];
    }
    __syncthreads();

    const float b0    = sb[0];
    const float lvl0  = sb[64];
    const float lvl1a = sb[32];
    const float lvl1b = sb[96];

    float loss1 = 0.0f;
    unsigned int cnt = 0;
    bool sawInvalid = false;

    const int base = batch * HW + blk * PPB;
    const float4* t4 = (const float4*)(tdm + base);
    const int4*   m4 = (const int4*)(mask + base);

    #pragma unroll
    for (int it = 0; it < PPB / (4 * TH); it++) {       // 2 iterations, 8 px/thread
        const int i = it * TH + tid;
        const float4 tv = t4[i];
        const int4   mv = m4[i];
        const float gv[4] = {tv.x, tv.y, tv.z, tv.w};
        const int   mk[4] = {mv.x, mv.y, mv.z, mv.w};
        #pragma unroll
        for (int k = 0; k < 4; k++) {
            const bool valid = (mk[k] != 0);
            const float g = valid ? fmaxf(gv[k], b0) : b0;
            const int s = ub7(g, lvl0, lvl1a, lvl1b, ez);
            loss1 += fminf(g - sb[s - 1], sb[s] - g);    // 0 for invalid (g==b0)
            if (valid) {
                cnt++;
                const int gi = __float_as_int(g);        // g>0: int order==float order
                if (gi > spmax[s]) atomicMax(&spmax[s], gi);   // monotonic: race-safe
                if (gi < spmin[s]) atomicMin(&spmin[s], gi);
            } else {
                sawInvalid = true;
            }
        }
    }
    if (sawInvalid) sflag = 1;                           // benign race
    __syncthreads();

    if (tid == 0 && sflag) {                             // one b0 update for all invalids
        const int s = ub7(b0, lvl0, lvl1a, lvl1b, ez);
        const int bi = __float_as_int(b0);
        if (bi > spmax[s]) atomicMax(&spmax[s], bi);
        if (bi < spmin[s]) atomicMin(&spmin[s], bi);
    }

    // block reduce loss1 & count
    #pragma unroll
    for (int off = 16; off; off >>= 1) {
        loss1 += __shfl_down_sync(0xFFFFFFFFu, loss1, off);
        cnt   += __shfl_down_sync(0xFFFFFFFFu, cnt,   off);
    }
    if ((tid & 31) == 0) { wl[tid >> 5] = loss1; wc[tid >> 5] = cnt; }
    __syncthreads();

    // publish partials
    if (tid == 0) {
        float L = 0.0f; unsigned int C = 0;
        #pragma unroll
        for (int w = 0; w < TH / 32; w++) { L += wl[w]; C += wc[w]; }
        g_pl1[bid] = L; g_pcnt[bid] = C;
    }
    for (int i = tid; i < NSEG; i += TH) {
        g_pmax[bid * NSEG + i] = spmax[i];
        g_pmin[bid * NSEG + i] = spmin[i];
    }
    __threadfence();
    if (tid == 0) s_tick = atomicAdd(&g_tick_b[batch], 1u);
    __syncthreads();
    if (s_tick != BPB - 1) return;

    // ---------------- batch finalizer (one block per batch) ----------------
    __threadfence();
    if (tid == 0) g_tick_b[batch] = 0;                   // reset for next replay

    __shared__ float pref[NSEG], suf[NSEG];
    for (int i = tid; i < 2 * NSEG; i += TH) {           // merge 24 partials/segment
        const int seg = (i < NSEG) ? i : (i - NSEG);
        const int mbase = (batch * BPB) * NSEG + seg;
        if (i < NSEG) {
            int mx = -1;
            #pragma unroll 8
            for (int b = 0; b < BPB; b++) mx = max(mx, g_pmax[mbase + b * NSEG]);
            pref[seg] = (mx == -1) ? -1e30f : __int_as_float(mx);
        } else {
            int mn = INF_BITS;
            #pragma unroll 8
            for (int b = 0; b < BPB; b++) mn = min(mn, g_pmin[mbase + b * NSEG]);
            suf[seg] = (mn == INF_BITS) ? 1e30f : __int_as_float(mn);
        }
    }
    float L = 0.0f; unsigned int C = 0;
    if (tid < 32) {
        if (tid < BPB) { L = g_pl1[batch * BPB + tid]; C = g_pcnt[batch * BPB + tid]; }
        #pragma unroll
        for (int off = 16; off; off >>= 1) {
            L += __shfl_down_sync(0xFFFFFFFFu, L, off);
            C += __shfl_down_sync(0xFFFFFFFFu, C, off);
        }
    }
    __syncthreads();

    // Parallel scans: pref = inclusive prefix-max, suf = inclusive suffix-min.
    #pragma unroll
    for (int off = 1; off < NSEG; off <<= 1) {           // 8 Hillis-Steele steps
        float a = 0.0f, bmin = 0.0f;
        if (tid < NSEG) {
            a = pref[tid];
            if (tid >= off) a = fmaxf(a, pref[tid - off]);
            bmin = suf[tid];
            if (tid + off < NSEG) bmin = fminf(bmin, suf[tid + off]);
        }
        __syncthreads();
        if (tid < NSEG) { pref[tid] = a; suf[tid] = bmin; }
        __syncthreads();
    }

    float v = 0.0f;
    if (tid < DB) {
        const float bj = sb[tid];
        v = fminf(bj - pref[tid], suf[tid + 1] - bj);    // exact per-bin min dist
    }
    #pragma unroll
    for (int off = 16; off; off >>= 1) v += __shfl_down_sync(0xFFFFFFFFu, v, off);
    __shared__ float wv[TH / 32];
    if ((tid & 31) == 0) wv[tid >> 5] = v;
    if (tid == 0) { wl[0] = L; wc[0] = C; }              // stash batch L/C
    __syncthreads();

    if (tid == 0) {
        const float loss2 = wv[0] + wv[1] + wv[2] + wv[3];
        g_bsum[batch] = wl[0] + loss2;
        g_bcnt[batch] = wc[0];
        __threadfence();
        const unsigned int t2 = atomicAdd(&g_tick_g, 1u);
        if (t2 == NB - 1) {                              // global finalizer
            g_tick_g = 0;
            __threadfence();
            unsigned int tot = 0;
            #pragma unroll
            for (int b = 0; b < NB; b++) tot += g_bcnt[b];
            const float inv = 1.0f / (float)tot;
            #pragma unroll
            for (int b = 0; b < NB; b++) out[b] = g_bsum[b] * inv;
        }
    }
}

extern "C" void kernel_launch(void* const* d_in, const int* in_sizes, int n_in,
                              void* d_out, int out_size) {
    const float* bins = (const float*)d_in[0];
    const float* tdm  = (const float*)d_in[1];
    const int*   msk  = (const int*)d_in[2];
    float*       out  = (float*)d_out;

    bcl_fused<<<NB * BPB, TH>>>(bins, tdm, msk, out);
}